// round 3
// baseline (speedup 1.0000x reference)
#include <cuda_runtime.h>
#include <math.h>

// Problem constants (fixed by reference)
#define B_   32
#define L_   16000
#define C_   4
#define CF_  5
#define G_   8          // B/GROUP_SIZE
#define LN2F 0.69314718055994531f

// Kernel configs
#define K1_GRID 125
#define K1_BLK  128     // 125*128 = 16000 loci exactly
#define K2_LC   72      // 72*32*(16+4+1) = 48384 B <= 48KB static smem
#define K2_GRID 223     // 223*72 = 16056 >= 16000
#define K3_GRID 500
#define K3_BLK  256     // 500*256 = 128000 = G_*L_ exactly

// ---- scratch (device globals; no allocation allowed) ----
__device__ float          g_h[B_ * L_];        // 0.5*(ent + ln2*psum) per (batch, locus)
__device__ unsigned char  g_lbl[B_ * L_];      // argmax(y_true) per (batch, locus)
__device__ float          g_pred[G_ * L_];     // pred_alt per (group, locus)
__device__ unsigned char  g_altp[G_ * L_];     // alt_cnt | (nonmiss<<4)
__device__ int            g_nm[G_];            // per-group nonmiss locus count
__device__ float          g_ce_part[K1_GRID * (K1_BLK / 32)];  // 500 warp partials
__device__ float          g_r2_part[K3_GRID];
__device__ float          g_js_part[K2_GRID * 1024];
__device__ float          g_cnt_part[K2_GRID * 1024];

// ---- k0: zero the int accumulators (everything else fully overwritten) ----
__global__ void k0_init() {
    if (threadIdx.x < G_) g_nm[threadIdx.x] = 0;
}

// ---- k1: per-locus pass. labels, CE, h (entropy term), r2 partials ----
__global__ void __launch_bounds__(K1_BLK) k1_per_locus(
    const float4* __restrict__ logits4,   // (B, L) of float4 (C=4)
    const float4* __restrict__ prob4,
    const float*  __restrict__ ytrue)     // (B, L, 5)
{
    const int l = blockIdx.x * K1_BLK + threadIdx.x;  // exact: 0..15999

    float ce_acc = 0.0f;
    float pred_g = 0.0f;
    int   alt_g  = 0;
    int   nm_g   = 0;

#pragma unroll 4
    for (int i = 0; i < B_; ++i) {
        const size_t gi = (size_t)i * L_ + l;

        // label from exact one-hot: lbl = sum(c * y[c])
        const float* yt = ytrue + gi * CF_;
        float lf = yt[1] + 2.0f * yt[2] + 3.0f * yt[3] + 4.0f * yt[4];
        int lbl = (int)(lf + 0.5f);
        g_lbl[gi] = (unsigned char)lbl;

        // cross entropy (ignore_index = 4), reduction = sum
        float4 lg = logits4[gi];
        float m  = fmaxf(fmaxf(lg.x, lg.y), fmaxf(lg.z, lg.w));
        float se = __expf(lg.x - m) + __expf(lg.y - m) +
                   __expf(lg.z - m) + __expf(lg.w - m);
        float lse = m + __logf(se);
        if (lbl != 4) {
            float sel = (lbl == 0) ? lg.x : (lbl == 1) ? lg.y : (lbl == 2) ? lg.z : lg.w;
            ce_acc += lse - sel;
        }

        // entropy folding term for the evo kernel
        float4 p = prob4[gi];
        float a = fmaxf(p.x, 1e-7f), b = fmaxf(p.y, 1e-7f);
        float c = fmaxf(p.z, 1e-7f), d = fmaxf(p.w, 1e-7f);
        float ent = a * __logf(a) + b * __logf(b) + c * __logf(c) + d * __logf(d);
        float ps  = a + b + c + d;
        g_h[gi] = 0.5f * (ent + LN2F * ps);

        // r2 partials (uses RAW prob for pred_alt)
        pred_g += p.y + p.z + p.w;
        alt_g  += (lbl >= 1 && lbl <= 3);
        nm_g   |= (lbl != 4);

        if ((i & 3) == 3) {
            int g = i >> 2;
            g_pred[(size_t)g * L_ + l] = 0.25f * pred_g;
            g_altp[(size_t)g * L_ + l] = (unsigned char)(alt_g | (nm_g << 4));
            unsigned bal = __ballot_sync(0xFFFFFFFFu, nm_g != 0);
            if ((threadIdx.x & 31) == 0) atomicAdd(&g_nm[g], __popc(bal));
            pred_g = 0.0f; alt_g = 0; nm_g = 0;
        }
    }

    // warp-reduce CE, one deterministic partial per warp
#pragma unroll
    for (int o = 16; o > 0; o >>= 1) ce_acc += __shfl_xor_sync(0xFFFFFFFFu, ce_acc, o);
    if ((threadIdx.x & 31) == 0)
        g_ce_part[blockIdx.x * (K1_BLK / 32) + (threadIdx.x >> 5)] = ce_acc;
}

// ---- k2: pairwise JS. CTA = all 1024 (i,j) pairs over a locus chunk ----
__global__ void __launch_bounds__(1024, 1) k2_evo(const float4* __restrict__ prob4)
{
    __shared__ float4        s_pc[K2_LC * 32];
    __shared__ float         s_h [K2_LC * 32];
    __shared__ unsigned char s_lb[K2_LC * 32];

    const int l0   = blockIdx.x * K2_LC;
    const int nloc = min(K2_LC, L_ - l0);

    // stage chunk: layout [locus][batch], conflict-free shared stores
    for (int idx = threadIdx.x; idx < nloc * 32; idx += 1024) {
        int i  = idx & 31;
        int ll = idx >> 5;
        size_t gi = (size_t)i * L_ + l0 + ll;
        float4 p = prob4[gi];
        p.x = fmaxf(p.x, 1e-7f); p.y = fmaxf(p.y, 1e-7f);
        p.z = fmaxf(p.z, 1e-7f); p.w = fmaxf(p.w, 1e-7f);
        s_pc[idx] = p;
        s_h[idx]  = g_h[gi];
        s_lb[idx] = g_lbl[gi];
    }
    __syncthreads();

    const int i = threadIdx.x >> 5;   // p_i loads broadcast within warp
    const int j = threadIdx.x & 31;   // p_j loads conflict-free (16B stride)
    float js = 0.0f, cnt = 0.0f;

    for (int ll = 0; ll < nloc; ++ll) {
        const int base = ll << 5;
        int li = s_lb[base + i];
        int lj = s_lb[base + j];
        // branchless mask: density 16% but whole-warp-inactive prob ~0.1%
        float msk = (li == lj && li != 4) ? 1.0f : 0.0f;
        float4 pi = s_pc[base + i];
        float4 pj = s_pc[base + j];
        float s0 = pi.x + pj.x, s1 = pi.y + pj.y;
        float s2 = pi.z + pj.z, s3 = pi.w + pj.w;
        // cross = sum s*log(s/2) = slog - ln2*(psum_i+psum_j); ln2 term folded into h
        float slog = s0 * __logf(s0) + s1 * __logf(s1) +
                     s2 * __logf(s2) + s3 * __logf(s3);
        js  += msk * (s_h[base + i] + s_h[base + j] - 0.5f * slog);
        cnt += msk;
    }

    g_js_part [blockIdx.x * 1024 + threadIdx.x] = js;
    g_cnt_part[blockIdx.x * 1024 + threadIdx.x] = cnt;
}

// ---- k3: r2 per (group, locus), deterministic block partials ----
__global__ void __launch_bounds__(K3_BLK) k3_r2()
{
    const int t = blockIdx.x * K3_BLK + threadIdx.x;  // exact: 0..127999, g-major
    const int g = t / L_;

    float cntg = fmaxf(4.0f * (float)g_nm[g], 1.0f);
    unsigned char pk = g_altp[t];
    float alt = (float)(pk & 15);
    bool nonmiss = (pk & 16) != 0;
    float af2 = nonmiss ? (alt / cntg) : 0.5f;

    float r2 = 0.0f;
    if (nonmiss && af2 != 0.0f && af2 != 1.0f) {
        float den = fmaxf(af2 * (1.0f - af2), 0.01f);
        float d   = g_pred[t] - af2;
        r2 = d * d / den;
    }

#pragma unroll
    for (int o = 16; o > 0; o >>= 1) r2 += __shfl_xor_sync(0xFFFFFFFFu, r2, o);
    __shared__ float sh[K3_BLK / 32];
    if ((threadIdx.x & 31) == 0) sh[threadIdx.x >> 5] = r2;
    __syncthreads();
    if (threadIdx.x == 0) {
        float s = 0.0f;
#pragma unroll
        for (int k = 0; k < K3_BLK / 32; ++k) s += sh[k];
        g_r2_part[blockIdx.x] = s;
    }
}

// ---- k4: combine everything into the scalar output ----
__global__ void __launch_bounds__(1024) k4_final(const float* __restrict__ yevo,
                                                 float* __restrict__ out)
{
    const int t = threadIdx.x;       // t = i*32 + j; warp == row i

    float js_s = 0.0f, cnt_s = 0.0f;
    for (int b = 0; b < K2_GRID; ++b) {
        js_s  += g_js_part [b * 1024 + t];
        cnt_s += g_cnt_part[b * 1024 + t];
    }
    float jsv = js_s / fmaxf(cnt_s, 1.0f);

    float w  = __expf(-yevo[t]);
    float rs = w;
#pragma unroll
    for (int o = 16; o > 0; o >>= 1) rs += __shfl_xor_sync(0xFFFFFFFFu, rs, o);
    float term = (w / (rs + 1e-8f)) * jsv;

    float ce_v = (t < K1_GRID * (K1_BLK / 32)) ? g_ce_part[t] : 0.0f;
    float r2_v = (t < K3_GRID) ? g_r2_part[t] : 0.0f;

    float v0 = term, v1 = ce_v, v2 = r2_v;
#pragma unroll
    for (int o = 16; o > 0; o >>= 1) {
        v0 += __shfl_xor_sync(0xFFFFFFFFu, v0, o);
        v1 += __shfl_xor_sync(0xFFFFFFFFu, v1, o);
        v2 += __shfl_xor_sync(0xFFFFFFFFu, v2, o);
    }
    __shared__ float sh[3][32];
    if ((t & 31) == 0) { sh[0][t >> 5] = v0; sh[1][t >> 5] = v1; sh[2][t >> 5] = v2; }
    __syncthreads();
    if (t == 0) {
        float evo = 0.0f, ce = 0.0f, r2 = 0.0f;
#pragma unroll
        for (int k = 0; k < 32; ++k) { evo += sh[0][k]; ce += sh[1][k]; r2 += sh[2][k]; }
        if (!isfinite(evo)) evo = 0.0f;
        // total = ce_loss + r2_loss + evo_loss; r2_loss = -sum*GROUP_SIZE/B = -0.125*sum
        out[0] = ce - 0.125f * r2 + evo;
    }
}

extern "C" void kernel_launch(void* const* d_in, const int* in_sizes, int n_in,
                              void* d_out, int out_size)
{
    // metadata order: logits (B,L,C) f32, prob (B,L,C) f32,
    //                 y_true (B,L,CF) f32, y_evo_mat (B,B) f32
    const float* logits = (const float*)d_in[0];
    const float* prob   = (const float*)d_in[1];
    const float* ytrue  = (const float*)d_in[2];
    const float* yevo   = (const float*)d_in[3];

    k0_init<<<1, 32>>>();
    k1_per_locus<<<K1_GRID, K1_BLK>>>((const float4*)logits, (const float4*)prob, ytrue);
    k2_evo<<<K2_GRID, 1024>>>((const float4*)prob);
    k3_r2<<<K3_GRID, K3_BLK>>>();
    k4_final<<<1, 1024>>>(yevo, (float*)d_out);
}

// round 4
// speedup vs baseline: 2.0125x; 2.0125x over previous
#include <cuda_runtime.h>
#include <math.h>

// Problem constants (fixed by reference)
#define B_     32
#define L_     16000
#define CF_    5
#define LN2F   0.69314718055994531f
#define HLN2F  0.34657359027997264f   // 0.5*ln2

// k2 tiling: 56 loci per CTA (even, so the symmetry split is exact),
// 286 CTAs = ceil(16000/56); last CTA has 40 loci (also even).
#define LC     56
#define NB     286
#define NBPAD  288
#define SPAD   33                      // smem stride per locus (33 elems, pad kills conflicts)

// ---- scratch (device globals; no allocation allowed) ----
__device__ float          g_js_part [1024 * NBPAD];  // [pair][cta]
__device__ float          g_cnt_part[1024 * NBPAD];
__device__ float          g_pred[L_ * 8];            // [locus][group]
__device__ unsigned char  g_altp[L_ * 8];            // alt_cnt | (nonmiss<<4)
__device__ int            g_nm_part[NB * 8];         // [cta][group]
__device__ float          g_ce_part[NB * 32];        // [cta][warp]
__device__ float          g_js [1024], g_cnt[1024];
__device__ float          g_r2_blk[32], g_ce_blk[32];

// ============================================================================
// k2: fused per-locus pass (labels, CE, h, r2 partials) + symmetric pairwise JS
// ============================================================================
__global__ void __launch_bounds__(1024) k2_mega(
    const float4* __restrict__ logits4,   // (B, L) float4 (C=4)
    const float4* __restrict__ prob4,
    const float*  __restrict__ ytrue)     // (B, L, 5)
{
    __shared__ float4        s_pc[LC * SPAD];   // clamped prob
    __shared__ float         s_h [LC * SPAD];   // 0.5*(ent + ln2*psum)
    __shared__ unsigned char s_lb[LC * SPAD];   // label
    __shared__ int           s_nm[8];

    const int tid  = threadIdx.x;
    const int lane = tid & 31;
    const int l0   = blockIdx.x * LC;
    const int nloc = min(LC, L_ - l0);           // 56 or 40 (always even)
    const int n32  = nloc * 32;

    if (tid < 8) s_nm[tid] = 0;
    __syncthreads();

    // ---- staging: coalesced global loads (lanes walk consecutive loci) ----
    float ce_acc = 0.0f;
    for (int e = tid; e < n32; e += 1024) {
        int i  = e / nloc;          // batch
        int ll = e - i * nloc;      // local locus
        int l  = l0 + ll;
        size_t gi = (size_t)i * L_ + l;

        // label from exact one-hot
        const float* yt = ytrue + gi * CF_;
        float lf = yt[1] + 2.0f * yt[2] + 3.0f * yt[3] + 4.0f * yt[4];
        int lbl = (int)(lf + 0.5f);
        s_lb[ll * SPAD + i] = (unsigned char)lbl;

        // cross entropy (ignore_index = 4)
        float4 lg = logits4[gi];
        float m  = fmaxf(fmaxf(lg.x, lg.y), fmaxf(lg.z, lg.w));
        float se = __expf(lg.x - m) + __expf(lg.y - m) +
                   __expf(lg.z - m) + __expf(lg.w - m);
        if (lbl != 4) {
            float sel = (lbl == 0) ? lg.x : (lbl == 1) ? lg.y : (lbl == 2) ? lg.z : lg.w;
            ce_acc += (m + LN2F * __log2f(se)) - sel;
        }

        // clamped prob + entropy-folding term
        float4 p = prob4[gi];
        float a = fmaxf(p.x, 1e-7f), b = fmaxf(p.y, 1e-7f);
        float c = fmaxf(p.z, 1e-7f), d = fmaxf(p.w, 1e-7f);
        float ent2 = a * __log2f(a) + b * __log2f(b) +
                     c * __log2f(c) + d * __log2f(d);
        s_pc[ll * SPAD + i] = make_float4(a, b, c, d);
        s_h [ll * SPAD + i] = HLN2F * (ent2 + (a + b + c + d));
    }

    // per-warp CE partial (deterministic)
#pragma unroll
    for (int o = 16; o > 0; o >>= 1) ce_acc += __shfl_xor_sync(0xFFFFFFFFu, ce_acc, o);
    if (lane == 0) g_ce_part[blockIdx.x * 32 + (tid >> 5)] = ce_acc;

    __syncthreads();

    // ---- r2 group partials from staged smem: 8 groups x nloc tasks ----
    if (tid < nloc * 8) {
        int g  = tid & 7;
        int ll = tid >> 3;
        int base = ll * SPAD + g * 4;
        float pred = 0.0f;
        int alt = 0, nm = 0;
#pragma unroll
        for (int q = 0; q < 4; ++q) {
            float4 p = s_pc[base + q];
            pred += p.y + p.z + p.w;
            int lb = s_lb[base + q];
            alt += (lb >= 1 && lb <= 3);
            nm  |= (lb != 4);
        }
        int l = l0 + ll;
        g_pred[l * 8 + g] = 0.25f * pred;
        g_altp[l * 8 + g] = (unsigned char)(alt | (nm << 4));
        if (nm) atomicAdd(&s_nm[g], 1);     // int atomics: deterministic value
    }
    __syncthreads();
    if (tid < 8) g_nm_part[blockIdx.x * 8 + tid] = s_nm[tid];

    // ---- symmetric pairwise JS: thread (i,j); j>=i does [0,H), j<i does [H,nloc) ----
    const int i = tid >> 5;
    const int j = lane;
    const int H = nloc >> 1;
    const int start = (j < i) ? H : 0;

    float js = 0.0f, cnt = 0.0f;
    for (int k = 0; k < H; ++k) {
        const int base = (start + k) * SPAD;
        int li = s_lb[base + i];
        int lj = s_lb[base + j];
        float msk = (li == lj && li != 4) ? 1.0f : 0.0f;
        float4 pi = s_pc[base + i];
        float4 pj = s_pc[base + j];
        float s0 = pi.x + pj.x, s1 = pi.y + pj.y;
        float s2 = pi.z + pj.z, s3 = pi.w + pj.w;
        // sum s*log(s/2) = ln2*(s*log2 s) - ln2*psum; psum term folded into h
        float slog2 = s0 * __log2f(s0) + s1 * __log2f(s1) +
                      s2 * __log2f(s2) + s3 * __log2f(s3);
        js  += msk * (s_h[base + i] + s_h[base + j] - HLN2F * slog2);
        cnt += msk;
    }

    g_js_part [tid * NBPAD + blockIdx.x] = js;
    g_cnt_part[tid * NBPAD + blockIdx.x] = cnt;
}

// ============================================================================
// k4a: 32 blocks. Reduce js/cnt partials per pair; nm totals; r2; CE partials.
// ============================================================================
__global__ void __launch_bounds__(1024) k4a_reduce()
{
    const int tid  = threadIdx.x;
    const int w    = tid >> 5;
    const int lane = tid & 31;

    // -- per-pair js/cnt over CTAs (warp per pair, coalesced row scan) --
    {
        int t = blockIdx.x * 32 + w;
        float js = 0.0f, cnt = 0.0f;
        for (int b = lane; b < NB; b += 32) {
            js  += g_js_part [t * NBPAD + b];
            cnt += g_cnt_part[t * NBPAD + b];
        }
#pragma unroll
        for (int o = 16; o > 0; o >>= 1) {
            js  += __shfl_xor_sync(0xFFFFFFFFu, js,  o);
            cnt += __shfl_xor_sync(0xFFFFFFFFu, cnt, o);
        }
        if (lane == 0) { g_js[t] = js; g_cnt[t] = cnt; }
    }

    // -- nm totals per group (warps 0..7) --
    __shared__ int s_nmtot[8];
    if (w < 8) {
        int nm = 0;
        for (int b = lane; b < NB; b += 32) nm += g_nm_part[b * 8 + w];
#pragma unroll
        for (int o = 16; o > 0; o >>= 1) nm += __shfl_xor_sync(0xFFFFFFFFu, nm, o);
        if (lane == 0) s_nmtot[w] = nm;
    }
    __syncthreads();

    // -- r2 over this block's slice of (locus, group) --
    float r2acc = 0.0f;
#pragma unroll
    for (int q = 0; q < 4; ++q) {
        int idx = blockIdx.x * 4096 + q * 1024 + tid;
        if (idx < L_ * 8) {
            int g = idx & 7;
            float cntg = fmaxf(4.0f * (float)s_nmtot[g], 1.0f);
            unsigned char pk = g_altp[idx];
            float alt = (float)(pk & 15);
            bool nonmiss = (pk & 16) != 0;
            float af2 = nonmiss ? (alt / cntg) : 0.5f;
            if (nonmiss && af2 != 0.0f && af2 != 1.0f) {
                float den = fmaxf(af2 * (1.0f - af2), 0.01f);
                float dd  = g_pred[idx] - af2;
                r2acc += dd * dd / den;
            }
        }
    }

    // -- CE partial slice: NB*32 = 9152 = 32 blocks x 286 --
    float ceacc = (tid < NB) ? g_ce_part[blockIdx.x * NB + tid] : 0.0f;

    // block-reduce r2acc + ceacc
#pragma unroll
    for (int o = 16; o > 0; o >>= 1) {
        r2acc += __shfl_xor_sync(0xFFFFFFFFu, r2acc, o);
        ceacc += __shfl_xor_sync(0xFFFFFFFFu, ceacc, o);
    }
    __shared__ float sh[2][32];
    if (lane == 0) { sh[0][w] = r2acc; sh[1][w] = ceacc; }
    __syncthreads();
    if (tid == 0) {
        float r2 = 0.0f, ce = 0.0f;
#pragma unroll
        for (int k = 0; k < 32; ++k) { r2 += sh[0][k]; ce += sh[1][k]; }
        g_r2_blk[blockIdx.x] = r2;
        g_ce_blk[blockIdx.x] = ce;
    }
}

// ============================================================================
// k4b: final scalar. Transpose-combine symmetric halves, evo weights, output.
// ============================================================================
__global__ void __launch_bounds__(1024) k4b_final(const float* __restrict__ yevo,
                                                  float* __restrict__ out)
{
    const int t = threadIdx.x;            // t = i*32 + j; warp = row i
    __shared__ float sj[1024], sc[1024];
    sj[t] = g_js[t];
    sc[t] = g_cnt[t];
    __syncthreads();

    const int tT = (t & 31) * 32 + (t >> 5);
    float jsv = (sj[t] + sj[tT]) / fmaxf(sc[t] + sc[tT], 1.0f);

    float wgt = __expf(-yevo[t]);
    float rs = wgt;
#pragma unroll
    for (int o = 16; o > 0; o >>= 1) rs += __shfl_xor_sync(0xFFFFFFFFu, rs, o);
    float term = (wgt / (rs + 1e-8f)) * jsv;

    float r2_v = (t < 32) ? g_r2_blk[t] : 0.0f;
    float ce_v = (t < 32) ? g_ce_blk[t] : 0.0f;

    float v0 = term, v1 = ce_v, v2 = r2_v;
#pragma unroll
    for (int o = 16; o > 0; o >>= 1) {
        v0 += __shfl_xor_sync(0xFFFFFFFFu, v0, o);
        v1 += __shfl_xor_sync(0xFFFFFFFFu, v1, o);
        v2 += __shfl_xor_sync(0xFFFFFFFFu, v2, o);
    }
    __shared__ float sh[3][32];
    const int w = t >> 5, lane = t & 31;
    if (lane == 0) { sh[0][w] = v0; sh[1][w] = v1; sh[2][w] = v2; }
    __syncthreads();
    if (t == 0) {
        float evo = 0.0f, ce = 0.0f, r2 = 0.0f;
#pragma unroll
        for (int k = 0; k < 32; ++k) { evo += sh[0][k]; ce += sh[1][k]; r2 += sh[2][k]; }
        if (!isfinite(evo)) evo = 0.0f;
        out[0] = ce - 0.125f * r2 + evo;   // r2_loss = -sum*GS/B = -0.125*sum
    }
}

extern "C" void kernel_launch(void* const* d_in, const int* in_sizes, int n_in,
                              void* d_out, int out_size)
{
    const float* logits = (const float*)d_in[0];
    const float* prob   = (const float*)d_in[1];
    const float* ytrue  = (const float*)d_in[2];
    const float* yevo   = (const float*)d_in[3];

    k2_mega <<<NB, 1024>>>((const float4*)logits, (const float4*)prob, ytrue);
    k4a_reduce<<<32, 1024>>>();
    k4b_final <<<1, 1024>>>(yevo, (float*)d_out);
}

// round 5
// speedup vs baseline: 2.0976x; 1.0423x over previous
#include <cuda_runtime.h>
#include <cuda_fp16.h>
#include <math.h>

// Problem constants (fixed by reference)
#define B_     32
#define L_     16000
#define CF_    5
#define LN2F   0.69314718055994531f
#define HLN2F  0.34657359027997264f   // 0.5*ln2

// k2 tiling: 56 loci per CTA (even => exact symmetric split). 286 CTAs.
#define LC     56
#define NB     286
#define SROW   33                      // smem row stride (elements), kills store conflicts

// ---- scratch (device globals; no allocation allowed) ----
__device__ float          g_js_part [NB * 1024];   // [cta][pair]  (coalesced writes)
__device__ float          g_cnt_part[NB * 1024];
__device__ float          g_pred[L_ * 8];          // [locus][group]
__device__ unsigned char  g_altp[L_ * 8];          // alt_cnt | (nonmiss<<4)
__device__ int            g_nm_part[NB * 8];       // [cta][group]
__device__ float          g_ce_part[NB * 32];      // [cta][warp]
__device__ float          g_js4 [4 * 1024], g_cnt4[4 * 1024];  // quarter-reduced
__device__ float          g_r2_blk[32], g_ce_blk[32];

// ============================================================================
// k2: fused staging (labels, CE, h', fp16 probs) + symmetric pairwise JS
// ============================================================================
__global__ void __launch_bounds__(1024) k2_mega(
    const float4* __restrict__ logits4,   // (B, L) float4 (C=4)
    const float4* __restrict__ prob4,
    const float*  __restrict__ ytrue)     // (B, L, 5)
{
    __shared__ uint2    s_p[LC * SROW];   // 4 x fp16 clamped prob
    __shared__ unsigned s_m[LC * SROW];   // (bf16 h' << 16) | label
    __shared__ int      s_nm[8];

    const int tid  = threadIdx.x;
    const int lane = tid & 31;
    const int l0   = blockIdx.x * LC;
    const int nloc = min(LC, L_ - l0);     // 56 or 40 (even)
    const int n32  = nloc * 32;

    if (tid < 8) s_nm[tid] = 0;
    __syncthreads();

    // ---- staging: coalesced global loads (lanes walk consecutive loci) ----
    float ce_acc = 0.0f;
    for (int e = tid; e < n32; e += 1024) {
        int i  = e / nloc;                // batch
        int ll = e - i * nloc;            // local locus
        size_t gi = (size_t)i * L_ + l0 + ll;

        // label from exact one-hot
        const float* yt = ytrue + gi * CF_;
        float lf = yt[1] + 2.0f * yt[2] + 3.0f * yt[3] + 4.0f * yt[4];
        int lbl = (int)(lf + 0.5f);

        // cross entropy (ignore_index = 4)
        float4 lg = logits4[gi];
        float m  = fmaxf(fmaxf(lg.x, lg.y), fmaxf(lg.z, lg.w));
        float se = __expf(lg.x - m) + __expf(lg.y - m) +
                   __expf(lg.z - m) + __expf(lg.w - m);
        if (lbl != 4) {
            float sel = (lbl == 0) ? lg.x : (lbl == 1) ? lg.y : (lbl == 2) ? lg.z : lg.w;
            ce_acc += (m + LN2F * __log2f(se)) - sel;
        }

        // clamped prob, h' = sum p*log2 p + sum p  (all ln2 factors folded out)
        float4 p = prob4[gi];
        float a = fmaxf(p.x, 1e-7f), b = fmaxf(p.y, 1e-7f);
        float c = fmaxf(p.z, 1e-7f), d = fmaxf(p.w, 1e-7f);
        float hp = a * __log2f(a) + b * __log2f(b) +
                   c * __log2f(c) + d * __log2f(d) + (a + b + c + d);
        unsigned hb = (__float_as_uint(hp) + 0x8000u) & 0xFFFF0000u;  // bf16 RN-ish

        __half2 p01 = __floats2half2_rn(a, b);
        __half2 p23 = __floats2half2_rn(c, d);
        int idx = ll * SROW + i;
        s_p[idx] = make_uint2(reinterpret_cast<unsigned&>(p01),
                              reinterpret_cast<unsigned&>(p23));
        s_m[idx] = hb | (unsigned)lbl;
    }

    // per-warp CE partial (deterministic)
#pragma unroll
    for (int o = 16; o > 0; o >>= 1) ce_acc += __shfl_xor_sync(0xFFFFFFFFu, ce_acc, o);
    if (lane == 0) g_ce_part[blockIdx.x * 32 + (tid >> 5)] = ce_acc;

    __syncthreads();

    // ---- r2 group partials from staged smem ----
    if (tid < nloc * 8) {
        int g  = tid & 7;
        int ll = tid >> 3;
        int base = ll * SROW + g * 4;
        float pred = 0.0f;
        int alt = 0, nm = 0;
#pragma unroll
        for (int q = 0; q < 4; ++q) {
            uint2 u = s_p[base + q];
            float2 f01 = __half22float2(reinterpret_cast<__half2&>(u.x));
            float2 f23 = __half22float2(reinterpret_cast<__half2&>(u.y));
            pred += f01.y + f23.x + f23.y;
            int lb = s_m[base + q] & 0xFF;
            alt += (lb >= 1 && lb <= 3);
            nm  |= (lb != 4);
        }
        int l = l0 + ll;
        g_pred[l * 8 + g] = 0.25f * pred;
        g_altp[l * 8 + g] = (unsigned char)(alt | (nm << 4));
        if (nm) atomicAdd(&s_nm[g], 1);   // int atomics: deterministic value
    }
    __syncthreads();
    if (tid < 8) g_nm_part[blockIdx.x * 8 + tid] = s_nm[tid];

    // ---- symmetric pairwise JS: (i,j) j>=i does [0,H); j<i does [H,nloc) ----
    const int i = tid >> 5;
    const int j = lane;
    const int H = nloc >> 1;
    const int start = (j < i) ? H : 0;

    float js = 0.0f, cnt = 0.0f;
#pragma unroll 2
    for (int k = 0; k < H; ++k) {
        const int row = (start + k) * SROW;
        unsigned wi = s_m[row + i];           // broadcast
        unsigned li = wi & 0xFFu;
        if (li == 4u) continue;               // warp-uniform skip (20% of loci)
        unsigned wj = s_m[row + j];
        float msk = ((wj & 0xFFu) == li) ? 1.0f : 0.0f;
        uint2 ui = s_p[row + i];              // broadcast
        uint2 uj = s_p[row + j];
        __half2 s01 = __hadd2(reinterpret_cast<__half2&>(ui.x),
                              reinterpret_cast<__half2&>(uj.x));
        __half2 s23 = __hadd2(reinterpret_cast<__half2&>(ui.y),
                              reinterpret_cast<__half2&>(uj.y));
        float2 f01 = __half22float2(s01);
        float2 f23 = __half22float2(s23);
        float slog2 = f01.x * __log2f(f01.x) + f01.y * __log2f(f01.y) +
                      f23.x * __log2f(f23.x) + f23.y * __log2f(f23.y);
        float hsum = __uint_as_float(wi & 0xFFFF0000u) +
                     __uint_as_float(wj & 0xFFFF0000u);
        js  = fmaf(msk, hsum - slog2, js);    // scaled by HLN2F in k4b
        cnt += msk;
    }

    g_js_part [blockIdx.x * 1024 + tid] = js;   // coalesced
    g_cnt_part[blockIdx.x * 1024 + tid] = cnt;
}

// ============================================================================
// k4a: grid 48 x 256. Blocks 0-15: pair partial scans (4 quarters x 4 chunks).
//      Blocks 16-47: nm totals (redundant), r2, CE partials.
// ============================================================================
__global__ void __launch_bounds__(256) k4a_reduce()
{
    const int tid = threadIdx.x;
    const int bid = blockIdx.x;

    if (bid < 16) {
        const int q  = bid >> 2;                  // quarter of cta range
        const int t  = (bid & 3) * 256 + tid;     // pair id
        const int b0 = q * 72;
        const int b1 = min(b0 + 72, NB);
        float js = 0.0f, cnt = 0.0f;
#pragma unroll 4
        for (int b = b0; b < b1; ++b) {           // coalesced: consecutive t
            js  += g_js_part [b * 1024 + t];
            cnt += g_cnt_part[b * 1024 + t];
        }
        g_js4 [q * 1024 + t] = js;
        g_cnt4[q * 1024 + t] = cnt;
        return;
    }

    const int rb   = bid - 16;                    // 0..31
    const int w    = tid >> 5;
    const int lane = tid & 31;

    __shared__ int s_nmtot[8];
    if (w < 8) {
        int nm = 0;
        for (int b = lane; b < NB; b += 32) nm += g_nm_part[b * 8 + w];
#pragma unroll
        for (int o = 16; o > 0; o >>= 1) nm += __shfl_xor_sync(0xFFFFFFFFu, nm, o);
        if (lane == 0) s_nmtot[w] = nm;
    }
    __syncthreads();

    float r2acc = 0.0f;
    for (int idx = rb * 256 + tid; idx < L_ * 8; idx += 8192) {
        int g = idx & 7;
        float cntg = fmaxf(4.0f * (float)s_nmtot[g], 1.0f);
        unsigned char pk = g_altp[idx];
        float alt = (float)(pk & 15);
        bool nonmiss = (pk & 16) != 0;
        float af2 = nonmiss ? (alt / cntg) : 0.5f;
        if (nonmiss && af2 != 0.0f && af2 != 1.0f) {
            float den = fmaxf(af2 * (1.0f - af2), 0.01f);
            float dd  = g_pred[idx] - af2;
            r2acc += dd * dd / den;
        }
    }

    float ceacc = 0.0f;
    for (int idx = rb * 256 + tid; idx < NB * 32; idx += 8192) ceacc += g_ce_part[idx];

#pragma unroll
    for (int o = 16; o > 0; o >>= 1) {
        r2acc += __shfl_xor_sync(0xFFFFFFFFu, r2acc, o);
        ceacc += __shfl_xor_sync(0xFFFFFFFFu, ceacc, o);
    }
    __shared__ float sh[2][8];
    if (lane == 0) { sh[0][w] = r2acc; sh[1][w] = ceacc; }
    __syncthreads();
    if (tid == 0) {
        float r2 = 0.0f, ce = 0.0f;
#pragma unroll
        for (int k = 0; k < 8; ++k) { r2 += sh[0][k]; ce += sh[1][k]; }
        g_r2_blk[rb] = r2;
        g_ce_blk[rb] = ce;
    }
}

// ============================================================================
// k4b: final scalar. Quarter-combine, transpose symmetric halves, evo weights.
// ============================================================================
__global__ void __launch_bounds__(1024) k4b_final(const float* __restrict__ yevo,
                                                  float* __restrict__ out)
{
    const int t = threadIdx.x;            // t = i*32 + j; warp = row i
    __shared__ float sj[1024], sc[1024];
    sj[t] = g_js4[t] + g_js4[1024 + t] + g_js4[2048 + t] + g_js4[3072 + t];
    sc[t] = g_cnt4[t] + g_cnt4[1024 + t] + g_cnt4[2048 + t] + g_cnt4[3072 + t];
    __syncthreads();

    const int tT = (t & 31) * 32 + (t >> 5);
    float jsv = HLN2F * (sj[t] + sj[tT]) / fmaxf(sc[t] + sc[tT], 1.0f);

    float wgt = __expf(-yevo[t]);
    float rs = wgt;
#pragma unroll
    for (int o = 16; o > 0; o >>= 1) rs += __shfl_xor_sync(0xFFFFFFFFu, rs, o);
    float term = (wgt / (rs + 1e-8f)) * jsv;

    float r2_v = (t < 32) ? g_r2_blk[t] : 0.0f;
    float ce_v = (t < 32) ? g_ce_blk[t] : 0.0f;

    float v0 = term, v1 = ce_v, v2 = r2_v;
#pragma unroll
    for (int o = 16; o > 0; o >>= 1) {
        v0 += __shfl_xor_sync(0xFFFFFFFFu, v0, o);
        v1 += __shfl_xor_sync(0xFFFFFFFFu, v1, o);
        v2 += __shfl_xor_sync(0xFFFFFFFFu, v2, o);
    }
    __shared__ float sh[3][32];
    const int w = t >> 5, lane = t & 31;
    if (lane == 0) { sh[0][w] = v0; sh[1][w] = v1; sh[2][w] = v2; }
    __syncthreads();
    if (t == 0) {
        float evo = 0.0f, ce = 0.0f, r2 = 0.0f;
#pragma unroll
        for (int k = 0; k < 32; ++k) { evo += sh[0][k]; ce += sh[1][k]; r2 += sh[2][k]; }
        if (!isfinite(evo)) evo = 0.0f;
        out[0] = ce - 0.125f * r2 + evo;   // r2_loss = -sum*GS/B = -0.125*sum
    }
}

extern "C" void kernel_launch(void* const* d_in, const int* in_sizes, int n_in,
                              void* d_out, int out_size)
{
    const float* logits = (const float*)d_in[0];
    const float* prob   = (const float*)d_in[1];
    const float* ytrue  = (const float*)d_in[2];
    const float* yevo   = (const float*)d_in[3];

    k2_mega   <<<NB, 1024>>>((const float4*)logits, (const float4*)prob, ytrue);
    k4a_reduce<<<48, 256>>>();
    k4b_final <<<1, 1024>>>(yevo, (float*)d_out);
}